// round 3
// baseline (speedup 1.0000x reference)
#include <cuda_runtime.h>
#include <math.h>

#define Bn 8
#define Hn 512
#define Ln 4096
#define NSt 32   // N/2 states

// Intermediate y = gelu(conv(u,k) + D*u), shape (B,H,L). Static device scratch
// (no runtime allocation allowed).
__device__ float g_y[Bn * Hn * Ln];

// ---------------------------------------------------------------------------
// Kernel 1: diagonal SSM recurrence + D skip + exact (erf) GELU.
// One warp per (b,h); lane n owns complex state n. Per step:
//   s = w*s + u ;  p = Re(2*Ck * s) ; butterfly-sum over 32 lanes.
// GELU is applied in bulk every 32 steps (each lane keeps the step it "owns"),
// then one coalesced 128B store.
// ---------------------------------------------------------------------------
__global__ void __launch_bounds__(128)
s4d_recurrence(const float* __restrict__ u,
               const float* __restrict__ log_dt,
               const float* __restrict__ C_re,
               const float* __restrict__ C_im,
               const float* __restrict__ log_A_real,
               const float* __restrict__ A_imag,
               const float* __restrict__ Dv)
{
    int warp = (blockIdx.x * blockDim.x + threadIdx.x) >> 5;
    int lane = threadIdx.x & 31;
    if (warp >= Bn * Hn) return;
    int b = warp / Hn;
    int h = warp % Hn;

    // Per-state constants
    float dt  = expf(log_dt[h]);
    float Are = -expf(log_A_real[h * NSt + lane]);
    float Aim = A_imag[h * NSt + lane];
    float dAr = Are * dt, dAi = Aim * dt;
    float er  = expf(dAr);
    float sv, cv;
    sincosf(dAi, &sv, &cv);
    float wr = er * cv, wi = er * sv;          // w = exp(dt*A)
    float cr = C_re[h * NSt + lane];
    float ci = C_im[h * NSt + lane];
    // Ck = C*(w-1)/A, fold the 2x output factor in.
    float m1r = wr - 1.0f;
    float nr  = cr * m1r - ci * wi;
    float ni  = cr * wi  + ci * m1r;
    float inv = 2.0f / (Are * Are + Aim * Aim);
    float Ckr = (nr * Are + ni * Aim) * inv;
    float Cki = (ni * Are - nr * Aim) * inv;

    float Dh = Dv[h];
    const float* up = u   + (size_t)(b * Hn + h) * Ln;
    float*       yp = g_y + (size_t)(b * Hn + h) * Ln;

    float sr = 0.0f, si = 0.0f;
    for (int l0 = 0; l0 < Ln; l0 += 32) {
        float uv = up[l0 + lane];          // coalesced; broadcast via shfl below
        float ysave = 0.0f;
        #pragma unroll
        for (int j = 0; j < 32; ++j) {
            float uj  = __shfl_sync(0xffffffffu, uv, j);
            // complex state update: s = w*s + u
            float t   = fmaf(wr, sr, uj);
            float nsi = fmaf(wr, si, wi * sr);
            sr = fmaf(-wi, si, t);
            si = nsi;
            // per-lane output contribution
            float p = fmaf(Ckr, sr, -(Cki * si));
            // full-warp sum (result on all lanes)
            p += __shfl_xor_sync(0xffffffffu, p, 16);
            p += __shfl_xor_sync(0xffffffffu, p, 8);
            p += __shfl_xor_sync(0xffffffffu, p, 4);
            p += __shfl_xor_sync(0xffffffffu, p, 2);
            p += __shfl_xor_sync(0xffffffffu, p, 1);
            float yraw = fmaf(Dh, uj, p);
            if (lane == j) ysave = yraw;   // lane j keeps step l0+j
        }
        // exact GELU: x * Phi(x), once per 32 steps per lane
        yp[l0 + lane] = ysave * normcdff(ysave);
    }
}

// ---------------------------------------------------------------------------
// Kernel 2: 1x1 conv (2H x H GEMM over channels) + bias + GLU, fused.
// out[b,h,l] = (Wa@y + ba) * sigmoid(Wg@y + bg)
// 64 h-rows x 128 l-cols per block, TK=16, packed f32x2 FMAs (2x fp32 rate).
// ---------------------------------------------------------------------------
#define TM 64
#define TN 128
#define TK 16

__device__ __forceinline__ unsigned long long pack2(float lo, float hi) {
    unsigned long long r;
    asm("mov.b64 %0, {%1, %2};" : "=l"(r) : "f"(lo), "f"(hi));
    return r;
}
__device__ __forceinline__ void unpack2(unsigned long long v, float& lo, float& hi) {
    asm("mov.b64 {%0, %1}, %2;" : "=f"(lo), "=f"(hi) : "l"(v));
}
__device__ __forceinline__ unsigned long long fma2(unsigned long long a,
                                                   unsigned long long b,
                                                   unsigned long long c) {
    unsigned long long d;
    asm("fma.rn.f32x2 %0, %1, %2, %3;" : "=l"(d) : "l"(a), "l"(b), "l"(c));
    return d;
}

__global__ void __launch_bounds__(256)
s4d_glu_gemm(const float* __restrict__ Wm,
             const float* __restrict__ bias,
             float* __restrict__ out)
{
    __shared__ __align__(16) float Was[TK][68];   // [k][m], padded
    __shared__ __align__(16) float Wgs[TK][68];
    __shared__ __align__(16) float Ys[TK][TN];    // [k][c]

    int b  = blockIdx.z;
    int h0 = blockIdx.y * TM;
    int c0 = blockIdx.x * TN;
    int tid = threadIdx.x;
    int tm = tid >> 4;        // 0..15 -> 4 h-rows each
    int tn = tid & 15;        // 0..15 -> 8 l-cols each

    unsigned long long accA[4][4], accG[4][4];
    #pragma unroll
    for (int i = 0; i < 4; i++)
        #pragma unroll
        for (int j = 0; j < 4; j++) { accA[i][j] = 0ull; accG[i][j] = 0ull; }

    int lm = tid >> 2;            // 0..63   W tile row
    int lk = (tid & 3) * 4;       // 0,4,8,12 W tile k offset
    int yr = tid >> 5;            // 0..7    Y tile row
    int yc = (tid & 31) * 4;      // Y tile col

    const float* yb = g_y + (size_t)b * Hn * Ln;

    for (int kt = 0; kt < Hn; kt += TK) {
        float4 va = *(const float4*)&Wm[(size_t)(h0 + lm) * Hn + kt + lk];
        float4 vg = *(const float4*)&Wm[(size_t)(Hn + h0 + lm) * Hn + kt + lk];
        float4 y0 = *(const float4*)&yb[(size_t)(kt + yr) * Ln + c0 + yc];
        float4 y1 = *(const float4*)&yb[(size_t)(kt + yr + 8) * Ln + c0 + yc];
        Was[lk + 0][lm] = va.x; Was[lk + 1][lm] = va.y;
        Was[lk + 2][lm] = va.z; Was[lk + 3][lm] = va.w;
        Wgs[lk + 0][lm] = vg.x; Wgs[lk + 1][lm] = vg.y;
        Wgs[lk + 2][lm] = vg.z; Wgs[lk + 3][lm] = vg.w;
        *(float4*)&Ys[yr][yc]     = y0;
        *(float4*)&Ys[yr + 8][yc] = y1;
        __syncthreads();

        #pragma unroll
        for (int k = 0; k < TK; ++k) {
            ulonglong2 p0 = *(const ulonglong2*)&Ys[k][tn * 8];
            ulonglong2 p1 = *(const ulonglong2*)&Ys[k][tn * 8 + 4];
            float4 wa = *(const float4*)&Was[k][tm * 4];
            float4 wg = *(const float4*)&Wgs[k][tm * 4];
            unsigned long long wwa[4] = { pack2(wa.x, wa.x), pack2(wa.y, wa.y),
                                          pack2(wa.z, wa.z), pack2(wa.w, wa.w) };
            unsigned long long wwg[4] = { pack2(wg.x, wg.x), pack2(wg.y, wg.y),
                                          pack2(wg.z, wg.z), pack2(wg.w, wg.w) };
            #pragma unroll
            for (int i = 0; i < 4; i++) {
                accA[i][0] = fma2(wwa[i], p0.x, accA[i][0]);
                accA[i][1] = fma2(wwa[i], p0.y, accA[i][1]);
                accA[i][2] = fma2(wwa[i], p1.x, accA[i][2]);
                accA[i][3] = fma2(wwa[i], p1.y, accA[i][3]);
                accG[i][0] = fma2(wwg[i], p0.x, accG[i][0]);
                accG[i][1] = fma2(wwg[i], p0.y, accG[i][1]);
                accG[i][2] = fma2(wwg[i], p1.x, accG[i][2]);
                accG[i][3] = fma2(wwg[i], p1.y, accG[i][3]);
            }
        }
        __syncthreads();
    }

    // epilogue: bias + GLU
    #pragma unroll
    for (int i = 0; i < 4; i++) {
        int hh = h0 + tm * 4 + i;
        float ba = bias[hh];
        float bg = bias[Hn + hh];
        float o[8];
        #pragma unroll
        for (int j = 0; j < 4; j++) {
            float a0, a1, g0, g1;
            unpack2(accA[i][j], a0, a1);
            unpack2(accG[i][j], g0, g1);
            a0 += ba; a1 += ba; g0 += bg; g1 += bg;
            o[2 * j]     = a0 / (1.0f + expf(-g0));
            o[2 * j + 1] = a1 / (1.0f + expf(-g1));
        }
        float* op = out + (size_t)(b * Hn + hh) * Ln + c0 + tn * 8;
        *(float4*)op       = make_float4(o[0], o[1], o[2], o[3]);
        *(float4*)(op + 4) = make_float4(o[4], o[5], o[6], o[7]);
    }
}

// ---------------------------------------------------------------------------
extern "C" void kernel_launch(void* const* d_in, const int* in_sizes, int n_in,
                              void* d_out, int out_size)
{
    const float* u          = (const float*)d_in[0];
    const float* log_dt     = (const float*)d_in[1];
    const float* C_re       = (const float*)d_in[2];
    const float* C_im       = (const float*)d_in[3];
    const float* log_A_real = (const float*)d_in[4];
    const float* A_imag     = (const float*)d_in[5];
    const float* D          = (const float*)d_in[6];
    const float* W          = (const float*)d_in[7];
    const float* bias       = (const float*)d_in[8];
    float* out = (float*)d_out;

    // 4096 (b,h) warps, 4 warps per block
    s4d_recurrence<<<(Bn * Hn) / 4, 128>>>(u, log_dt, C_re, C_im,
                                           log_A_real, A_imag, D);

    dim3 grid(Ln / TN, Hn / TM, Bn);   // (32, 8, 8)
    s4d_glu_gemm<<<grid, 256>>>(W, bias, out);
}